// round 15
// baseline (speedup 1.0000x reference)
#include <cuda_runtime.h>
#include <cuda_bf16.h>
#include <math.h>
#include <stdint.h>

// Problem constants
#define BB 8
#define LL 1024
#define DD 1024
#define KK 128
#define TROWS 1000
#define MPAD 1024
#define SCALING 0.08838834764831845f   // 128^-0.5

// ---------------- device scratch (no allocation allowed) -------------------
__device__ __align__(16) __nv_bfloat16 g_A1[MPAD * DD];    // bf16 time_table
__device__ __align__(16) __nv_bfloat16 g_Ah[MPAD * DD];    // bf16 silu(h)
__device__ __align__(16) __nv_bfloat16 g_W1[DD * DD];      // bf16 W1 [K][N]
__device__ __align__(16) __nv_bfloat16 g_W2[DD * DD];      // bf16 W2 [K][N]
__device__ __align__(16) __nv_bfloat16 g_tmlpb[MPAD * DD]; // bf16 mlp out
__device__ __align__(16) __nv_bfloat16 g_embb[160 * DD];   // bf16 embed table
__device__ __align__(16) __nv_bfloat16 g_atb[512 * DD];    // bf16 atom table
__device__ __align__(16) __nv_bfloat16 g_part[BB * LL * DD]; // embed+atom partial
__device__ __align__(16) float g_v[DD];
__device__ float g_s[BB * LL];

// ---------------- small helpers --------------------------------------------
__device__ __forceinline__ uint32_t packbf2(float a, float b) {
    __nv_bfloat162 t;
    t.x = __float2bfloat16(a);
    t.y = __float2bfloat16(b);
    return *(uint32_t*)&t;
}
__device__ __forceinline__ void mma_bf16(float* c, const uint32_t* a,
                                         uint32_t b0, uint32_t b1) {
    asm volatile(
        "mma.sync.aligned.m16n8k16.row.col.f32.bf16.bf16.f32 "
        "{%0,%1,%2,%3}, {%4,%5,%6,%7}, {%8,%9}, {%0,%1,%2,%3};"
        : "+f"(c[0]), "+f"(c[1]), "+f"(c[2]), "+f"(c[3])
        : "r"(a[0]), "r"(a[1]), "r"(a[2]), "r"(a[3]), "r"(b0), "r"(b1));
}
__device__ __forceinline__ void ldsm_x4(uint32_t* r, uint32_t addr) {
    asm volatile("ldmatrix.sync.aligned.m8n8.x4.shared.b16 {%0,%1,%2,%3}, [%4];"
                 : "=r"(r[0]), "=r"(r[1]), "=r"(r[2]), "=r"(r[3]) : "r"(addr));
}
__device__ __forceinline__ void ldsm_x4_t(uint32_t* r, uint32_t addr) {
    asm volatile("ldmatrix.sync.aligned.m8n8.x4.trans.shared.b16 {%0,%1,%2,%3}, [%4];"
                 : "=r"(r[0]), "=r"(r[1]), "=r"(r[2]), "=r"(r[3]) : "r"(addr));
}
#define CP16(dst, src) \
    asm volatile("cp.async.cg.shared.global [%0], [%1], 16;" \
                 :: "r"(dst), "l"(src) : "memory")
#define CP_COMMIT() asm volatile("cp.async.commit_group;" ::: "memory")
#define CP_WAIT2()  asm volatile("cp.async.wait_group 2;" ::: "memory")

// packed bf16x2 accumulate: a[0..3] += u (8 bf16 lanes)
__device__ __forceinline__ void hacc4(__nv_bfloat162* a, uint4 u) {
    a[0] = __hadd2(a[0], *(__nv_bfloat162*)&u.x);
    a[1] = __hadd2(a[1], *(__nv_bfloat162*)&u.y);
    a[2] = __hadd2(a[2], *(__nv_bfloat162*)&u.z);
    a[3] = __hadd2(a[3], *(__nv_bfloat162*)&u.w);
}

// ---------------- L1: cast A1+W1+embed+atab, compute v ----------------------
// blocks [0,1024): ttab  [1024,2048): w1  [2048,2208): embed
// [2208,2720): atab  [2720,2724): v
__global__ void prep0_kernel(const float* __restrict__ ttab,
                             const float* __restrict__ w1,
                             const float* __restrict__ embed,
                             const float* __restrict__ atab,
                             const float* __restrict__ pew,
                             const float* __restrict__ pfw)
{
    int blk = blockIdx.x;
    int tid = threadIdx.x;
    if (blk >= 2720) {
        int d = (blk - 2720) * 256 + tid;
        float acc = 0.f;
#pragma unroll 8
        for (int k = 0; k < KK; k++)
            acc += pew[k] * pfw[k * DD + d];
        g_v[d] = acc;
        return;
    }
    int i = blk * 256 + tid;   // float4 index
    const float4* src;
    __nv_bfloat16* dst;
    int off;
    if (i < 262144) {
        int m = i >> 8;
        float4 v = (m < TROWS) ? ((const float4*)ttab)[i]
                               : make_float4(0.f, 0.f, 0.f, 0.f);
        *(uint2*)(g_A1 + (size_t)i * 4) =
            make_uint2(packbf2(v.x, v.y), packbf2(v.z, v.w));
        return;
    } else if (i < 524288) { src = (const float4*)w1;    dst = g_W1;   off = i - 262144; }
    else if (i < 565248)   { src = (const float4*)embed; dst = g_embb; off = i - 524288; }
    else                   { src = (const float4*)atab;  dst = g_atb;  off = i - 565248; }
    float4 v = src[off];
    *(uint2*)(dst + (size_t)off * 4) = make_uint2(packbf2(v.x, v.y), packbf2(v.z, v.w));
}

// ---------------- L2/L3: heterogeneous mid kernel ---------------------------
// blocks [0,256):       bf16 GEMM (64x64 tile, 4 warps 2m x 2n)
// blocks [256,1280):    s[b,q] attention scalars     (L2 only)
// blocks [1280,9472):   per-token embed+atom partial (L2 only)
// blocks [9472,11520):  w2 cast                      (L2 only)
#define PITCH_A 80
#define PITCH_B 144
#define OFF_B 5120
#define STG 9728
#define DSMEM (4 * STG)   // 38912
__global__ void __launch_bounds__(128, 2)
mid_kernel(const float* __restrict__ bias, int stage,
           const float* __restrict__ w2,
           const float* __restrict__ pos,
           const int* __restrict__ token,
           const int* __restrict__ node_attr,
           const int* __restrict__ ismol)
{
    extern __shared__ __align__(16) char smem[];
    const int blk = blockIdx.x;
    const int tid = threadIdx.x;

    if (blk >= 9472) {
        // ---- w2 cast: 262144 float4 ----
        int i = (blk - 9472) * 128 + tid;
        float4 v = ((const float4*)w2)[i];
        *(uint2*)(g_W2 + (size_t)i * 4) =
            make_uint2(packbf2(v.x, v.y), packbf2(v.z, v.w));
        return;
    }

    if (blk >= 1280) {
        // ---- partial: g_part[bl] = embb[tok] (+ sum atb[idx]) ----
        __shared__ int hidx[8];
        __shared__ int htok, hmol;
        int bl = blk - 1280;
        if (tid < 8) hidx[tid] = node_attr[bl * 9 + 1 + tid];
        else if (tid == 8) htok = token[bl];
        else if (tid == 9) hmol = ismol[bl >> 10];
        __syncthreads();
        int d = tid * 8;
        __nv_bfloat162 a[4];
        {
            uint4 e = *(const uint4*)(g_embb + (size_t)htok * DD + d);
            a[0] = *(__nv_bfloat162*)&e.x;
            a[1] = *(__nv_bfloat162*)&e.y;
            a[2] = *(__nv_bfloat162*)&e.z;
            a[3] = *(__nv_bfloat162*)&e.w;
        }
        if (hmol) {
#pragma unroll
            for (int j = 0; j < 8; j++)
                hacc4(a, *(const uint4*)(g_atb + (size_t)hidx[j] * DD + d));
        }
        uint4 o;
        o.x = *(uint32_t*)&a[0]; o.y = *(uint32_t*)&a[1];
        o.z = *(uint32_t*)&a[2]; o.w = *(uint32_t*)&a[3];
        *(uint4*)(g_part + (size_t)bl * DD + d) = o;
        return;
    }

    if (blk >= 256) {
        // ---- s blocks: 128 threads, 4 warps, 8 queries/block ----
        float* px = (float*)smem;
        float* py = px + LL;
        float* pz = py + LL;
        float* rr = pz + LL;
        float* mm = rr + LL;
        float* red = mm + LL;     // [4][8][2]
        int sb = blk - 256;
        int b = sb >> 7;
        int q0 = (sb & 127) * 8;
        int w = tid >> 5, lane = tid & 31;

        for (int j = tid; j < LL; j += 128) {
            float x = pos[(size_t)(b * LL + j) * 3 + 0];
            float y = pos[(size_t)(b * LL + j) * 3 + 1];
            float z = pos[(size_t)(b * LL + j) * 3 + 2];
            px[j] = x; py[j] = y; pz[j] = z;
            float n2 = x * x + y * y + z * z;
            rr[j] = n2 * rsqrtf(fmaxf(n2, 1e-36f));
            mm[j] = (token[b * LL + j] != 0) ? 1.0f : 0.0f;
        }
        __syncthreads();

        float qx[8], qy[8], qz[8], se[8], sr[8];
#pragma unroll
        for (int qq = 0; qq < 8; qq++) {
            qx[qq] = px[q0 + qq]; qy[qq] = py[q0 + qq]; qz[qq] = pz[q0 + qq];
            se[qq] = 0.f; sr[qq] = 0.f;
        }
#pragma unroll
        for (int ch = 0; ch < 8; ch++) {
            int j = ch * 128 + w * 32 + lane;
            float kx = px[j], ky = py[j], kz = pz[j];
            float kr = rr[j], km = mm[j];
#pragma unroll
            for (int qq = 0; qq < 8; qq++) {
                float dx = kx - qx[qq], dy = ky - qy[qq], dz = kz - qz[qq];
                float n2 = dx * dx + dy * dy + dz * dz;
                float d = n2 * rsqrtf(fmaxf(n2, 1e-36f));
                float x = __fdividef(SCALING, d + 1.0f);
                float p = fmaf(x, 0.041666667f, 0.16666667f);   // exp Taylor
                p = fmaf(x, p, 0.5f);
                p = fmaf(x, p, 1.0f);
                float e = fmaf(x, p, 1.0f);
                float wt = e * km;
                se[qq] += wt;
                sr[qq] = fmaf(wt, kr, sr[qq]);
            }
        }
#pragma unroll
        for (int qq = 0; qq < 8; qq++) {
            float a = se[qq], c = sr[qq];
#pragma unroll
            for (int o = 16; o > 0; o >>= 1) {
                a += __shfl_xor_sync(0xffffffffu, a, o);
                c += __shfl_xor_sync(0xffffffffu, c, o);
            }
            if (lane == 0) { red[(w * 8 + qq) * 2] = a; red[(w * 8 + qq) * 2 + 1] = c; }
        }
        __syncthreads();
        if (tid < 8) {
            float SE = 0.f, SR = 0.f;
#pragma unroll
            for (int ww = 0; ww < 4; ww++) {
                SE += red[(ww * 8 + tid) * 2];
                SR += red[(ww * 8 + tid) * 2 + 1];
            }
            g_s[b * LL + q0 + tid] = (mm[q0 + tid] != 0.f) ? (SR / SE) : 0.0f;
        }
        return;
    }

    // ---- GEMM block ----
    const __nv_bfloat16* A = stage ? g_Ah : g_A1;
    const __nv_bfloat16* W = stage ? g_W2 : g_W1;

    const int lane = tid & 31;
    const int wid = tid >> 5;
    const int wm = wid & 1;
    const int wn = wid >> 1;
    const int m0 = (blk >> 4) * 64;
    const int n0 = (blk & 15) * 64;

    const uint32_t sbase = (uint32_t)__cvta_generic_to_shared(smem);

    uint32_t offA[2];
#pragma unroll
    for (int mf = 0; mf < 2; mf++)
        offA[mf] = (uint32_t)((wm * 32 + mf * 16 + (lane & 15)) * PITCH_A
                              + ((lane >> 4) & 1) * 16);
    const uint32_t offB = (uint32_t)(OFF_B + (lane & 15) * PITCH_B
                                     + (wn * 32 + ((lane >> 4) & 1) * 8) * 2);

    float acc[2][4][4];
#pragma unroll
    for (int i = 0; i < 2; i++)
#pragma unroll
        for (int j = 0; j < 4; j++)
#pragma unroll
            for (int q = 0; q < 4; q++) acc[i][j][q] = 0.f;

#define ISSUE(c_)                                                               \
    do {                                                                        \
        uint32_t st = sbase + ((c_) & 3) * STG;                                 \
        int k0 = (c_) * 32;                                                     \
        _Pragma("unroll")                                                       \
        for (int ii = 0; ii < 2; ii++) {                                        \
            int i = tid + ii * 128;                                             \
            int ra = i >> 2, qa = i & 3;                                        \
            CP16(st + ra * PITCH_A + qa * 16,                                   \
                 A + (size_t)(m0 + ra) * DD + k0 + qa * 8);                     \
            int rb = i >> 3, qb = i & 7;                                        \
            CP16(st + OFF_B + rb * PITCH_B + qb * 16,                           \
                 W + (size_t)(k0 + rb) * DD + n0 + qb * 8);                     \
        }                                                                       \
    } while (0)

    ISSUE(0); CP_COMMIT();
    ISSUE(1); CP_COMMIT();
    ISSUE(2); CP_COMMIT();

    for (int c = 0; c < 32; c++) {
        CP_WAIT2();
        __syncthreads();
        const uint32_t sst = sbase + (c & 3) * STG;

#pragma unroll
        for (int kk = 0; kk < 2; kk++) {
            uint32_t ah[2][4], bf[2][4];
#pragma unroll
            for (int mf = 0; mf < 2; mf++)
                ldsm_x4(ah[mf], sst + offA[mf] + kk * 32);
#pragma unroll
            for (int p = 0; p < 2; p++)
                ldsm_x4_t(bf[p], sst + offB + kk * 16 * PITCH_B + p * 32);
#pragma unroll
            for (int mf = 0; mf < 2; mf++)
#pragma unroll
                for (int nf = 0; nf < 4; nf++) {
                    const int p = nf >> 1, ix = (nf & 1) * 2;
                    mma_bf16(acc[mf][nf], ah[mf], bf[p][ix], bf[p][ix + 1]);
                }
        }
        if (c + 3 < 32) ISSUE(c + 3);
        CP_COMMIT();
    }

#pragma unroll
    for (int mf = 0; mf < 2; mf++) {
#pragma unroll
        for (int nf = 0; nf < 4; nf++) {
            int col = n0 + wn * 32 + nf * 8 + (lane & 3) * 2;
            float2 bb = *(const float2*)(bias + col);
            int r0 = m0 + wm * 32 + mf * 16 + (lane >> 2);
#pragma unroll
            for (int half = 0; half < 2; half++) {
                int r = r0 + half * 8;
                float v0 = acc[mf][nf][2 * half + 0] + bb.x;
                float v1 = acc[mf][nf][2 * half + 1] + bb.y;
                if (stage == 0) {
                    v0 = __fdividef(v0, 1.0f + __expf(-v0));
                    v1 = __fdividef(v1, 1.0f + __expf(-v1));
                    *(uint32_t*)(g_Ah + (size_t)r * DD + col) = packbf2(v0, v1);
                } else {
                    *(uint32_t*)(g_tmlpb + (size_t)r * DD + col) = packbf2(v0, v1);
                }
            }
        }
    }
}

// ---------------- L4 epilogue: stream partial + 1 gather + s*v --------------
__global__ void __launch_bounds__(1024, 2)
epilogue_kernel(const int* __restrict__ token,
                const int* __restrict__ tstep,
                float* __restrict__ out,
                int write_mask)
{
    __shared__ float sv[DD];
    __shared__ int stok[8], sts[8];
    __shared__ float ss[8];

    int tid = threadIdx.x;
    int bl0 = blockIdx.x * 8;

    sv[tid] = g_v[tid];
    if (tid < 24) {
        int t = tid / 3, f = tid - t * 3;
        int bl = bl0 + t;
        if (f == 0) stok[t] = token[bl];
        else if (f == 1) sts[t] = tstep[bl];
        else ss[t] = g_s[bl];
    }
    __syncthreads();

    int t = tid >> 7;
    int d = (tid & 127) * 8;
    int bl = bl0 + t;

    __nv_bfloat162 a[4];
    {
        uint4 p = *(const uint4*)(g_part + (size_t)bl * DD + d);   // streaming
        a[0] = *(__nv_bfloat162*)&p.x;
        a[1] = *(__nv_bfloat162*)&p.y;
        a[2] = *(__nv_bfloat162*)&p.z;
        a[3] = *(__nv_bfloat162*)&p.w;
    }
    hacc4(a, *(const uint4*)(g_tmlpb + (size_t)sts[t] * DD + d));  // one gather

    float acc[8];
    {
        float2 f;
        f = __bfloat1622float2(a[0]); acc[0] = f.x; acc[1] = f.y;
        f = __bfloat1622float2(a[1]); acc[2] = f.x; acc[3] = f.y;
        f = __bfloat1622float2(a[2]); acc[4] = f.x; acc[5] = f.y;
        f = __bfloat1622float2(a[3]); acc[6] = f.x; acc[7] = f.y;
    }
    if (stok[t] != 0) {
        float s = ss[t];
        float4 v0 = *(const float4*)(sv + d);
        float4 v1 = *(const float4*)(sv + d + 4);
        acc[0] = fmaf(s, v0.x, acc[0]); acc[1] = fmaf(s, v0.y, acc[1]);
        acc[2] = fmaf(s, v0.z, acc[2]); acc[3] = fmaf(s, v0.w, acc[3]);
        acc[4] = fmaf(s, v1.x, acc[4]); acc[5] = fmaf(s, v1.y, acc[5]);
        acc[6] = fmaf(s, v1.z, acc[6]); acc[7] = fmaf(s, v1.w, acc[7]);
    }
    float* o = out + (size_t)bl * DD + d;
    __stcs((float4*)o,       make_float4(acc[0], acc[1], acc[2], acc[3]));
    __stcs((float4*)(o + 4), make_float4(acc[4], acc[5], acc[6], acc[7]));

    if (write_mask && (tid & 127) == 0)
        out[(size_t)BB * LL * DD + bl] = (stok[t] == 0) ? 1.0f : 0.0f;
}

// ---------------------------------------------------------------------------
extern "C" void kernel_launch(void* const* d_in, const int* in_sizes, int n_in,
                              void* d_out, int out_size)
{
    const int*   token     = (const int*)d_in[0];
    const int*   node_attr = (const int*)d_in[1];
    const int*   ismol     = (const int*)d_in[2];
    const float* pos       = (const float*)d_in[3];
    const int*   tstep     = (const int*)d_in[4];
    const float* embed     = (const float*)d_in[5];
    const float* atab      = (const float*)d_in[6];
    const float* ttab      = (const float*)d_in[7];
    const float* w1        = (const float*)d_in[8];
    const float* b1        = (const float*)d_in[9];
    const float* w2        = (const float*)d_in[10];
    const float* b2        = (const float*)d_in[11];
    const float* pew       = (const float*)d_in[12];
    const float* pfw       = (const float*)d_in[13];
    float* out = (float*)d_out;

    cudaFuncSetAttribute(mid_kernel,
                         cudaFuncAttributeMaxDynamicSharedMemorySize, DSMEM);

    // L1: A1/W1/embed/atab casts + v
    prep0_kernel<<<2724, 256>>>(ttab, w1, embed, atab, pew, pfw);

    // L2: GEMM0 + s + per-token partial gathers + w2 cast (heterogeneous)
    mid_kernel<<<11520, 128, DSMEM>>>(b1, 0, w2, pos, token, node_attr, ismol);

    // L3: GEMM1 only
    mid_kernel<<<256, 128, DSMEM>>>(b2, 1, w2, pos, token, node_attr, ismol);

    // L4: lean epilogue (+mask tail)
    int write_mask = (out_size >= BB * LL * DD + BB * LL) ? 1 : 0;
    epilogue_kernel<<<BB * LL / 8, 1024>>>(token, tstep, out, write_mask);
}

// round 16
// speedup vs baseline: 1.1927x; 1.1927x over previous
#include <cuda_runtime.h>
#include <cuda_bf16.h>
#include <math.h>
#include <stdint.h>

// Problem constants
#define BB 8
#define LL 1024
#define DD 1024
#define KK 128
#define TROWS 1000
#define MPAD 1024
#define SCALING 0.08838834764831845f   // 128^-0.5

// ---------------- device scratch (no allocation allowed) -------------------
__device__ __align__(16) __nv_bfloat16 g_A1[MPAD * DD];    // bf16 time_table
__device__ __align__(16) __nv_bfloat16 g_Ah[MPAD * DD];    // bf16 silu(h)
__device__ __align__(16) __nv_bfloat16 g_W1[DD * DD];      // bf16 W1 [K][N]
__device__ __align__(16) __nv_bfloat16 g_W2[DD * DD];      // bf16 W2 [K][N]
__device__ __align__(16) __nv_bfloat16 g_tmlpb[MPAD * DD]; // bf16 mlp out
__device__ __align__(16) __nv_bfloat16 g_embb[160 * DD];   // bf16 embed table
__device__ __align__(16) __nv_bfloat16 g_atb[512 * DD];    // bf16 atom table
__device__ __align__(16) float g_v[DD];
__device__ float g_s[BB * LL];

// ---------------- small helpers --------------------------------------------
__device__ __forceinline__ uint32_t packbf2(float a, float b) {
    __nv_bfloat162 t;
    t.x = __float2bfloat16(a);
    t.y = __float2bfloat16(b);
    return *(uint32_t*)&t;
}
__device__ __forceinline__ void mma_bf16(float* c, const uint32_t* a,
                                         uint32_t b0, uint32_t b1) {
    asm volatile(
        "mma.sync.aligned.m16n8k16.row.col.f32.bf16.bf16.f32 "
        "{%0,%1,%2,%3}, {%4,%5,%6,%7}, {%8,%9}, {%0,%1,%2,%3};"
        : "+f"(c[0]), "+f"(c[1]), "+f"(c[2]), "+f"(c[3])
        : "r"(a[0]), "r"(a[1]), "r"(a[2]), "r"(a[3]), "r"(b0), "r"(b1));
}
__device__ __forceinline__ void ldsm_x4(uint32_t* r, uint32_t addr) {
    asm volatile("ldmatrix.sync.aligned.m8n8.x4.shared.b16 {%0,%1,%2,%3}, [%4];"
                 : "=r"(r[0]), "=r"(r[1]), "=r"(r[2]), "=r"(r[3]) : "r"(addr));
}
__device__ __forceinline__ void ldsm_x4_t(uint32_t* r, uint32_t addr) {
    asm volatile("ldmatrix.sync.aligned.m8n8.x4.trans.shared.b16 {%0,%1,%2,%3}, [%4];"
                 : "=r"(r[0]), "=r"(r[1]), "=r"(r[2]), "=r"(r[3]) : "r"(addr));
}
#define CP16(dst, src) \
    asm volatile("cp.async.cg.shared.global [%0], [%1], 16;" \
                 :: "r"(dst), "l"(src) : "memory")
#define CP_COMMIT() asm volatile("cp.async.commit_group;" ::: "memory")
#define CP_WAIT2()  asm volatile("cp.async.wait_group 2;" ::: "memory")

// packed bf16x2 accumulate: a[0..3] += u (8 bf16 lanes)
__device__ __forceinline__ void hacc4(__nv_bfloat162* a, uint4 u) {
    a[0] = __hadd2(a[0], *(__nv_bfloat162*)&u.x);
    a[1] = __hadd2(a[1], *(__nv_bfloat162*)&u.y);
    a[2] = __hadd2(a[2], *(__nv_bfloat162*)&u.z);
    a[3] = __hadd2(a[3], *(__nv_bfloat162*)&u.w);
}

// ---------------- L1: cast A1 + W1, compute v --------------------------------
__global__ void prep0_kernel(const float* __restrict__ ttab,
                             const float* __restrict__ w1,
                             const float* __restrict__ pew,
                             const float* __restrict__ pfw)
{
    int blk = blockIdx.x;
    int tid = threadIdx.x;
    if (blk >= 2048) {
        int d = (blk - 2048) * 256 + tid;
        float acc = 0.f;
#pragma unroll 8
        for (int k = 0; k < KK; k++)
            acc += pew[k] * pfw[k * DD + d];
        g_v[d] = acc;
        return;
    }
    int i = blk * 256 + tid;   // float4 index
    if (i < 262144) {
        int m = i >> 8;
        float4 v = (m < TROWS) ? ((const float4*)ttab)[i]
                               : make_float4(0.f, 0.f, 0.f, 0.f);
        *(uint2*)(g_A1 + (size_t)i * 4) =
            make_uint2(packbf2(v.x, v.y), packbf2(v.z, v.w));
    } else {
        int off = i - 262144;
        float4 v = ((const float4*)w1)[off];
        *(uint2*)(g_W1 + (size_t)off * 4) =
            make_uint2(packbf2(v.x, v.y), packbf2(v.z, v.w));
    }
}

// ---------------- L2/L3: heterogeneous mid kernel ---------------------------
// blocks [0,256):     bf16 GEMM (64x64 tile, 4 warps 2m x 2n)
// blocks [256,1280):  s[b,q] attention scalars   (L2 launch only)
// blocks [1280,4672): casts w2/embed/atab        (L2 launch only)
#define PITCH_A 80
#define PITCH_B 144
#define OFF_B 5120
#define STG 9728
#define DSMEM (4 * STG)   // 38912
__global__ void __launch_bounds__(128, 2)
mid_kernel(const float* __restrict__ bias, int stage,
           const float* __restrict__ w2,
           const float* __restrict__ embed,
           const float* __restrict__ atab,
           const float* __restrict__ pos,
           const int* __restrict__ token)
{
    extern __shared__ __align__(16) char smem[];
    const int blk = blockIdx.x;
    const int tid = threadIdx.x;

    if (blk >= 1280) {
        int i = (blk - 1280) * 128 + tid;
        const float4* src;
        __nv_bfloat16* dst;
        int off;
        if (i < 262144)      { src = (const float4*)w2;    dst = g_W2;   off = i; }
        else if (i < 303104) { src = (const float4*)embed; dst = g_embb; off = i - 262144; }
        else                 { src = (const float4*)atab;  dst = g_atb;  off = i - 303104; }
        float4 v = src[off];
        *(uint2*)(dst + (size_t)off * 4) =
            make_uint2(packbf2(v.x, v.y), packbf2(v.z, v.w));
        return;
    }

    if (blk >= 256) {
        // ---- s blocks: 128 threads, 4 warps, 8 queries/block ----
        float* px = (float*)smem;
        float* py = px + LL;
        float* pz = py + LL;
        float* rr = pz + LL;
        float* mm = rr + LL;
        float* red = mm + LL;     // [4][8][2]
        int sb = blk - 256;
        int b = sb >> 7;
        int q0 = (sb & 127) * 8;
        int w = tid >> 5, lane = tid & 31;

        for (int j = tid; j < LL; j += 128) {
            float x = pos[(size_t)(b * LL + j) * 3 + 0];
            float y = pos[(size_t)(b * LL + j) * 3 + 1];
            float z = pos[(size_t)(b * LL + j) * 3 + 2];
            px[j] = x; py[j] = y; pz[j] = z;
            float n2 = x * x + y * y + z * z;
            rr[j] = n2 * rsqrtf(fmaxf(n2, 1e-36f));
            mm[j] = (token[b * LL + j] != 0) ? 1.0f : 0.0f;
        }
        __syncthreads();

        float qx[8], qy[8], qz[8], se[8], sr[8];
#pragma unroll
        for (int qq = 0; qq < 8; qq++) {
            qx[qq] = px[q0 + qq]; qy[qq] = py[q0 + qq]; qz[qq] = pz[q0 + qq];
            se[qq] = 0.f; sr[qq] = 0.f;
        }
#pragma unroll
        for (int ch = 0; ch < 8; ch++) {
            int j = ch * 128 + w * 32 + lane;
            float kx = px[j], ky = py[j], kz = pz[j];
            float kr = rr[j], km = mm[j];
#pragma unroll
            for (int qq = 0; qq < 8; qq++) {
                float dx = kx - qx[qq], dy = ky - qy[qq], dz = kz - qz[qq];
                float n2 = dx * dx + dy * dy + dz * dz;
                float d = n2 * rsqrtf(fmaxf(n2, 1e-36f));
                float x = __fdividef(SCALING, d + 1.0f);
                float p = fmaf(x, 0.041666667f, 0.16666667f);   // exp Taylor
                p = fmaf(x, p, 0.5f);
                p = fmaf(x, p, 1.0f);
                float e = fmaf(x, p, 1.0f);
                float wt = e * km;
                se[qq] += wt;
                sr[qq] = fmaf(wt, kr, sr[qq]);
            }
        }
#pragma unroll
        for (int qq = 0; qq < 8; qq++) {
            float a = se[qq], c = sr[qq];
#pragma unroll
            for (int o = 16; o > 0; o >>= 1) {
                a += __shfl_xor_sync(0xffffffffu, a, o);
                c += __shfl_xor_sync(0xffffffffu, c, o);
            }
            if (lane == 0) { red[(w * 8 + qq) * 2] = a; red[(w * 8 + qq) * 2 + 1] = c; }
        }
        __syncthreads();
        if (tid < 8) {
            float SE = 0.f, SR = 0.f;
#pragma unroll
            for (int ww = 0; ww < 4; ww++) {
                SE += red[(ww * 8 + tid) * 2];
                SR += red[(ww * 8 + tid) * 2 + 1];
            }
            g_s[b * LL + q0 + tid] = (mm[q0 + tid] != 0.f) ? (SR / SE) : 0.0f;
        }
        return;
    }

    // ---- GEMM block ----
    const __nv_bfloat16* A = stage ? g_Ah : g_A1;
    const __nv_bfloat16* W = stage ? g_W2 : g_W1;

    const int lane = tid & 31;
    const int wid = tid >> 5;
    const int wm = wid & 1;
    const int wn = wid >> 1;
    const int m0 = (blk >> 4) * 64;
    const int n0 = (blk & 15) * 64;

    const uint32_t sbase = (uint32_t)__cvta_generic_to_shared(smem);

    uint32_t offA[2];
#pragma unroll
    for (int mf = 0; mf < 2; mf++)
        offA[mf] = (uint32_t)((wm * 32 + mf * 16 + (lane & 15)) * PITCH_A
                              + ((lane >> 4) & 1) * 16);
    const uint32_t offB = (uint32_t)(OFF_B + (lane & 15) * PITCH_B
                                     + (wn * 32 + ((lane >> 4) & 1) * 8) * 2);

    float acc[2][4][4];
#pragma unroll
    for (int i = 0; i < 2; i++)
#pragma unroll
        for (int j = 0; j < 4; j++)
#pragma unroll
            for (int q = 0; q < 4; q++) acc[i][j][q] = 0.f;

#define ISSUE(c_)                                                               \
    do {                                                                        \
        uint32_t st = sbase + ((c_) & 3) * STG;                                 \
        int k0 = (c_) * 32;                                                     \
        _Pragma("unroll")                                                       \
        for (int ii = 0; ii < 2; ii++) {                                        \
            int i = tid + ii * 128;                                             \
            int ra = i >> 2, qa = i & 3;                                        \
            CP16(st + ra * PITCH_A + qa * 16,                                   \
                 A + (size_t)(m0 + ra) * DD + k0 + qa * 8);                     \
            int rb = i >> 3, qb = i & 7;                                        \
            CP16(st + OFF_B + rb * PITCH_B + qb * 16,                           \
                 W + (size_t)(k0 + rb) * DD + n0 + qb * 8);                     \
        }                                                                       \
    } while (0)

    ISSUE(0); CP_COMMIT();
    ISSUE(1); CP_COMMIT();
    ISSUE(2); CP_COMMIT();

    for (int c = 0; c < 32; c++) {
        CP_WAIT2();
        __syncthreads();
        const uint32_t sst = sbase + (c & 3) * STG;

#pragma unroll
        for (int kk = 0; kk < 2; kk++) {
            uint32_t ah[2][4], bf[2][4];
#pragma unroll
            for (int mf = 0; mf < 2; mf++)
                ldsm_x4(ah[mf], sst + offA[mf] + kk * 32);
#pragma unroll
            for (int p = 0; p < 2; p++)
                ldsm_x4_t(bf[p], sst + offB + kk * 16 * PITCH_B + p * 32);
#pragma unroll
            for (int mf = 0; mf < 2; mf++)
#pragma unroll
                for (int nf = 0; nf < 4; nf++) {
                    const int p = nf >> 1, ix = (nf & 1) * 2;
                    mma_bf16(acc[mf][nf], ah[mf], bf[p][ix], bf[p][ix + 1]);
                }
        }
        if (c + 3 < 32) ISSUE(c + 3);
        CP_COMMIT();
    }

#pragma unroll
    for (int mf = 0; mf < 2; mf++) {
#pragma unroll
        for (int nf = 0; nf < 4; nf++) {
            int col = n0 + wn * 32 + nf * 8 + (lane & 3) * 2;
            float2 bb = *(const float2*)(bias + col);
            int r0 = m0 + wm * 32 + mf * 16 + (lane >> 2);
#pragma unroll
            for (int half = 0; half < 2; half++) {
                int r = r0 + half * 8;
                float v0 = acc[mf][nf][2 * half + 0] + bb.x;
                float v1 = acc[mf][nf][2 * half + 1] + bb.y;
                if (stage == 0) {
                    v0 = __fdividef(v0, 1.0f + __expf(-v0));
                    v1 = __fdividef(v1, 1.0f + __expf(-v1));
                    *(uint32_t*)(g_Ah + (size_t)r * DD + col) = packbf2(v0, v1);
                } else {
                    *(uint32_t*)(g_tmlpb + (size_t)r * DD + col) = packbf2(v0, v1);
                }
            }
        }
    }
}

// ---------------- fused epilogue: 8 tokens / 1024-thread block --------------
// round-10 shape (2048 thr/SM, regs<=32) + __stcs streamed output stores
__global__ void __launch_bounds__(1024, 2)
epilogue_kernel(const int* __restrict__ token,
                const int* __restrict__ node_attr,
                const int* __restrict__ ismol,
                const int* __restrict__ tstep,
                float* __restrict__ out,
                int write_mask)
{
    __shared__ float sv[DD];
    __shared__ int sidx[8][8];
    __shared__ int stok[8], sts[8], smol[8];
    __shared__ float ss[8];

    int tid = threadIdx.x;
    int bl0 = blockIdx.x * 8;

    sv[tid] = g_v[tid];
    if (tid < 96) {
        int t = tid / 12, f = tid - t * 12;
        int bl = bl0 + t;
        if (f < 8) sidx[t][f] = node_attr[bl * 9 + 1 + f];
        else if (f == 8) stok[t] = token[bl];
        else if (f == 9) sts[t] = tstep[bl];
        else if (f == 10) smol[t] = ismol[bl >> 10];
        else ss[t] = g_s[bl];
    }
    __syncthreads();

    int t = tid >> 7;
    int d = (tid & 127) * 8;
    int bl = bl0 + t;

    __nv_bfloat162 a[4];
    {
        uint4 e = *(const uint4*)(g_embb + (size_t)stok[t] * DD + d);
        a[0] = *(__nv_bfloat162*)&e.x;
        a[1] = *(__nv_bfloat162*)&e.y;
        a[2] = *(__nv_bfloat162*)&e.z;
        a[3] = *(__nv_bfloat162*)&e.w;
    }
    hacc4(a, *(const uint4*)(g_tmlpb + (size_t)sts[t] * DD + d));
    if (smol[t]) {
#pragma unroll
        for (int j = 0; j < 8; j++)
            hacc4(a, *(const uint4*)(g_atb + (size_t)sidx[t][j] * DD + d));
    }

    float acc[8];
    {
        float2 f;
        f = __bfloat1622float2(a[0]); acc[0] = f.x; acc[1] = f.y;
        f = __bfloat1622float2(a[1]); acc[2] = f.x; acc[3] = f.y;
        f = __bfloat1622float2(a[2]); acc[4] = f.x; acc[5] = f.y;
        f = __bfloat1622float2(a[3]); acc[6] = f.x; acc[7] = f.y;
    }
    if (stok[t] != 0) {
        float s = ss[t];
        float4 v0 = *(const float4*)(sv + d);
        float4 v1 = *(const float4*)(sv + d + 4);
        acc[0] = fmaf(s, v0.x, acc[0]); acc[1] = fmaf(s, v0.y, acc[1]);
        acc[2] = fmaf(s, v0.z, acc[2]); acc[3] = fmaf(s, v0.w, acc[3]);
        acc[4] = fmaf(s, v1.x, acc[4]); acc[5] = fmaf(s, v1.y, acc[5]);
        acc[6] = fmaf(s, v1.z, acc[6]); acc[7] = fmaf(s, v1.w, acc[7]);
    }
    float* o = out + (size_t)bl * DD + d;
    __stcs((float4*)o,       make_float4(acc[0], acc[1], acc[2], acc[3]));
    __stcs((float4*)(o + 4), make_float4(acc[4], acc[5], acc[6], acc[7]));

    if (write_mask && (tid & 127) == 0)
        out[(size_t)BB * LL * DD + bl] = (stok[t] == 0) ? 1.0f : 0.0f;
}

// ---------------------------------------------------------------------------
extern "C" void kernel_launch(void* const* d_in, const int* in_sizes, int n_in,
                              void* d_out, int out_size)
{
    const int*   token     = (const int*)d_in[0];
    const int*   node_attr = (const int*)d_in[1];
    const int*   ismol     = (const int*)d_in[2];
    const float* pos       = (const float*)d_in[3];
    const int*   tstep     = (const int*)d_in[4];
    const float* embed     = (const float*)d_in[5];
    const float* atab      = (const float*)d_in[6];
    const float* ttab      = (const float*)d_in[7];
    const float* w1        = (const float*)d_in[8];
    const float* b1        = (const float*)d_in[9];
    const float* w2        = (const float*)d_in[10];
    const float* b2        = (const float*)d_in[11];
    const float* pew       = (const float*)d_in[12];
    const float* pfw       = (const float*)d_in[13];
    float* out = (float*)d_out;

    cudaFuncSetAttribute(mid_kernel,
                         cudaFuncAttributeMaxDynamicSharedMemorySize, DSMEM);

    // L1: A1 + W1 casts + v
    prep0_kernel<<<2052, 256>>>(ttab, w1, pew, pfw);

    // L2: GEMM0 + s scalars + W2/embed/atab casts (heterogeneous)
    mid_kernel<<<4672, 128, DSMEM>>>(b1, 0, w2, embed, atab, pos, token);

    // L3: GEMM1 only
    mid_kernel<<<256, 128, DSMEM>>>(b2, 1, w2, embed, atab, pos, token);

    // L4: epilogue (+mask tail), 8 tokens / 1024 threads, __stcs stores
    int write_mask = (out_size >= BB * LL * DD + BB * LL) ? 1 : 0;
    epilogue_kernel<<<BB * LL / 8, 1024>>>(token, node_attr, ismol, tstep,
                                           out, write_mask);
}